// round 1
// baseline (speedup 1.0000x reference)
#include <cuda_runtime.h>
#include <cuda_bf16.h>

// DeformableConv2d fused kernel, sm_103a.
//
// Shapes: x[8,64,128,128], offset_w[1152,1,3,3], offset_b[1152],
//         deform_w[64,64,3,3], deform_b[64]  -> out[8,64,128,128] (fp32)
//
// Math exploited: softmax outputs dy,dx in (0,1) with integer sample base
// (h-1+ky, w-1+kx), so bilinear corners come from a fixed 4x4 zero-padded
// patch of x; zero padding == reference's validity masking.

#define Bq 8
#define Cc 64
#define Hh 128
#define Ww 128
#define CO 64
#define Pp 16   // positions (w) per CTA

// smem layout (floats)
#define SM_PATCH 0        // [64][4][20]                       = 5120
#define SM_EA    5120     // exp(e): [1152][20]                = 23040
#define SM_SAMP  28160    // sampled: [576][20]                = 11520
#define SM_UNI   39680    // union: {offw 10368 + offb 1152} / {wtT 64x68} / {obuf 1024}
#define SM_RED   51200    // [16][16]
#define SM_INVS  51456    // [16]
#define SM_TOTAL 51472
#define SMEM_BYTES (SM_TOTAL * 4)

__global__ __launch_bounds__(256, 1)
void deform_fused_kernel(const float* __restrict__ x,
                         const float* __restrict__ ow,
                         const float* __restrict__ obv,
                         const float* __restrict__ dw,
                         const float* __restrict__ db,
                         float* __restrict__ out)
{
    extern __shared__ float sm[];
    float* patch = sm + SM_PATCH;
    float* ea    = sm + SM_EA;
    float* samp  = sm + SM_SAMP;
    float* uni   = sm + SM_UNI;
    float* red   = sm + SM_RED;
    float* invS  = sm + SM_INVS;

    const int t  = threadIdx.x;
    const int w0 = blockIdx.x * Pp;
    const int h  = blockIdx.y;
    const int b  = blockIdx.z;

    // ---- Phase 0: stage offset weights + bias into smem (coalesced) ----
    {
        float* sow = uni;
        for (int i = t; i < 10368; i += 256) sow[i] = ow[i];
        for (int i = t; i < 1152;  i += 256) sow[10368 + i] = obv[i];
    }

    // ---- Phase 1: load 4x20 x-patch per channel, zero-padded ----
    {
        const float* xb = x + (size_t)b * Cc * Hh * Ww;
        for (int i = t; i < 5120; i += 256) {
            int c   = i / 80;
            int r2  = i % 80;
            int r   = r2 / 20;
            int col = r2 % 20;
            int gy = h - 1 + r;
            int gx = w0 - 1 + col;
            float v = 0.0f;
            if (gy >= 0 && gy < Hh && gx >= 0 && gx < Ww)
                v = xb[(size_t)c * (Hh * Ww) + gy * Ww + gx];
            patch[i] = v;   // i == (c*4+r)*20 + col
        }
    }
    __syncthreads();

    // ---- Phase 2: depthwise 3x3 conv -> e, store exp(e) ----
    // thread: c = t>>2 (64 channels), pq = t&3 (4 positions each)
    {
        const float* sow = uni;
        const float* sob = uni + 10368;
        const int c  = t >> 2;
        const int p0 = (t & 3) * 4;

        float pv[3][6];
        #pragma unroll
        for (int r = 0; r < 3; r++)
            #pragma unroll
            for (int s = 0; s < 6; s++)
                pv[r][s] = patch[(c * 4 + r) * 20 + p0 + s];

        #pragma unroll
        for (int j = 0; j < 18; j++) {
            const float* wj = sow + (c * 18 + j) * 9;
            const float bias = sob[c * 18 + j];
            float e0 = bias, e1 = bias, e2 = bias, e3 = bias;
            #pragma unroll
            for (int r = 0; r < 3; r++) {
                #pragma unroll
                for (int s = 0; s < 3; s++) {
                    float wv = wj[r * 3 + s];
                    e0 += wv * pv[r][s + 0];
                    e1 += wv * pv[r][s + 1];
                    e2 += wv * pv[r][s + 2];
                    e3 += wv * pv[r][s + 3];
                }
            }
            // |e| <= ~2, no max-subtraction needed for exp stability
            float4 ev = make_float4(__expf(e0), __expf(e1), __expf(e2), __expf(e3));
            *(float4*)&ea[(c * 18 + j) * 20 + p0] = ev;
        }
    }
    __syncthreads();

    // ---- Phase 3: softmax denominator per position -> invS ----
    {
        const int p = t & 15;
        const int g = t >> 4;
        float s = 0.0f;
        #pragma unroll 8
        for (int cj = g; cj < 1152; cj += 16)
            s += ea[cj * 20 + p];
        red[g * 16 + p] = s;
    }
    __syncthreads();
    if (t < 16) {
        float s = 0.0f;
        #pragma unroll
        for (int g = 0; g < 16; g++) s += red[g * 16 + t];
        invS[t] = 1.0f / s;
    }
    __syncthreads();

    // ---- Phase 4: bilinear-sampled values -> samp[ck][p] ----
    // thread: ckg = t>>2 (64 ck per step, 9 steps), 4 positions each
    {
        const int ckg = t >> 2;
        const int p0  = (t & 3) * 4;
        float4 isv4 = *(const float4*)&invS[p0];
        float isv[4] = {isv4.x, isv4.y, isv4.z, isv4.w};

        #pragma unroll
        for (int i = 0; i < 9; i++) {
            int ck = ckg + 64 * i;
            int c  = ck / 9;
            int k  = ck % 9;
            int ky = k / 3, kx = k % 3;
            const float* pr0 = &patch[(c * 4 + ky) * 20 + p0 + kx];
            const float* pr1 = pr0 + 20;
            float a0[5], a1[5];
            #pragma unroll
            for (int q = 0; q < 5; q++) { a0[q] = pr0[q]; a1[q] = pr1[q]; }

            float4 ayv = *(const float4*)&ea[(c * 18 + 2 * k)     * 20 + p0];
            float4 axv = *(const float4*)&ea[(c * 18 + 2 * k + 1) * 20 + p0];
            float ay[4] = {ayv.x, ayv.y, ayv.z, ayv.w};
            float ax[4] = {axv.x, axv.y, axv.z, axv.w};

            float res[4];
            #pragma unroll
            for (int q = 0; q < 4; q++) {
                float dy = ay[q] * isv[q];
                float dx = ax[q] * isv[q];
                float top = a0[q] + dx * (a0[q + 1] - a0[q]);
                float bot = a1[q] + dx * (a1[q + 1] - a1[q]);
                res[q] = top + dy * (bot - top);
            }
            *(float4*)&samp[ck * 20 + p0] = make_float4(res[0], res[1], res[2], res[3]);
        }
    }

    // ---- Phase 5: out[o][p] = sum_ck dw[o][ck] * samp[ck][p]  (k-split x2) ----
    float acc[4][2];
    #pragma unroll
    for (int a = 0; a < 4; a++) { acc[a][0] = 0.0f; acc[a][1] = 0.0f; }

    {
        float* wtT = uni;              // [64 ckl][68] transposed weight chunk
        const int ks = t >> 7;         // k-split half
        const int r  = t & 127;
        const int o0 = (r & 15) * 4;   // 4 outputs
        const int p0 = (r >> 4) * 2;   // 2 positions

        for (int cc = 0; cc < 9; cc++) {
            __syncthreads();           // protect previous consumers of uni/wtT
            const int ck0 = cc * 64;
            #pragma unroll
            for (int i = 0; i < 16; i++) {
                int idx = t + 256 * i;          // coalesced gmem read
                int o   = idx >> 6;
                int ckl = idx & 63;
                wtT[ckl * 68 + o] = dw[o * 576 + ck0 + ckl];
            }
            __syncthreads();
            #pragma unroll 8
            for (int kk = 0; kk < 32; kk++) {
                int ckl = ks * 32 + kk;
                float4 wv = *(const float4*)&wtT[ckl * 68 + o0];
                float2 sv = *(const float2*)&samp[(ck0 + ckl) * 20 + p0];
                acc[0][0] += wv.x * sv.x;  acc[0][1] += wv.x * sv.y;
                acc[1][0] += wv.y * sv.x;  acc[1][1] += wv.y * sv.y;
                acc[2][0] += wv.z * sv.x;  acc[2][1] += wv.z * sv.y;
                acc[3][0] += wv.w * sv.x;  acc[3][1] += wv.w * sv.y;
            }
        }
    }
    __syncthreads();

    // ---- Combine k-split halves, add bias, store ----
    {
        float* obuf = uni;             // [64][16], reuses wtT region
        const int ks = t >> 7;
        const int r  = t & 127;
        const int o0 = (r & 15) * 4;
        const int p0 = (r >> 4) * 2;

        if (ks == 1) {
            #pragma unroll
            for (int oo = 0; oo < 4; oo++)
                #pragma unroll
                for (int pp = 0; pp < 2; pp++)
                    obuf[(o0 + oo) * 16 + p0 + pp] = acc[oo][pp];
        }
        __syncthreads();
        if (ks == 0) {
            #pragma unroll
            for (int oo = 0; oo < 4; oo++) {
                int o = o0 + oo;
                float bias = __ldg(&db[o]);
                #pragma unroll
                for (int pp = 0; pp < 2; pp++) {
                    float v = acc[oo][pp] + obuf[o * 16 + p0 + pp] + bias;
                    out[(((size_t)b * CO + o) * Hh + h) * Ww + w0 + p0 + pp] = v;
                }
            }
        }
    }
}

extern "C" void kernel_launch(void* const* d_in, const int* in_sizes, int n_in,
                              void* d_out, int out_size)
{
    const float* x   = (const float*)d_in[0];   // [8,64,128,128]
    const float* ow  = (const float*)d_in[1];   // [1152,1,3,3]
    const float* obv = (const float*)d_in[2];   // [1152]
    const float* dw  = (const float*)d_in[3];   // [64,64,3,3]
    const float* db  = (const float*)d_in[4];   // [64]
    float* out = (float*)d_out;                 // [8,64,128,128]

    cudaFuncSetAttribute(deform_fused_kernel,
                         cudaFuncAttributeMaxDynamicSharedMemorySize, SMEM_BYTES);

    dim3 grid(Ww / Pp, Hh, Bq);   // (8, 128, 8) = 8192 CTAs
    deform_fused_kernel<<<grid, 256, SMEM_BYTES>>>(x, ow, obv, dw, db, out);
}